// round 15
// baseline (speedup 1.0000x reference)
#include <cuda_runtime.h>
#include <cuda_fp16.h>
#include <cstdint>
#include <math.h>
#include <mma.h>

using namespace nvcuda;

// ---------------------------------------------------------------------------
// PointFeatureAlignment: W[b,cell,g] (3-NN weights / 64) then
// Out[b,d,cell] = sum_g W[b,cell,g] * F[b,g,d]
// nn: R12 exact branchless top-3 with warp-vote skip (FROZEN — any change
//     that can alter selection is banned: R6/R10/R13 evidence).
// GEMM: wmma fp16 m16n16k16, fp32 accum, split-K=2, 3-STAGE cp.async ring
//       (the single delta vs the 59.9us baseline), float4-store epilogue,
//       g_P partial + add_kernel merge (R14's RED.F32 epilogue regressed).
// ---------------------------------------------------------------------------

#define IMAGE_SIZE 224
#define MAX_W_ELEMS  (4 * 784 * 512)
#define MAX_F_ELEMS  (4 * 512 * 384)
#define MAX_O_ELEMS  (4 * 384 * 784)

__device__ float  g_W[MAX_W_ELEMS];      // fp32 atomic accumulation target
__device__ __half g_Wh[MAX_W_ELEMS];     // fp16 copy for GEMM
__device__ __half g_Fh[MAX_F_ELEMS];     // fp16 features
__device__ float  g_P[MAX_O_ELEMS];      // split-K partial sums (slice 1)

__device__ __forceinline__ void cp_async16(uint32_t dst, const void* src, int src_bytes) {
    asm volatile("cp.async.cg.shared.global [%0], [%1], 16, %2;"
                 :: "r"(dst), "l"(src), "r"(src_bytes) : "memory");
}
__device__ __forceinline__ void cp_commit() {
    asm volatile("cp.async.commit_group;" ::: "memory");
}
__device__ __forceinline__ uint32_t smem_u32(const void* p) {
    uint32_t a;
    asm("{ .reg .u64 t; cvta.to.shared.u64 t, %1; cvt.u32.u64 %0, t; }"
        : "=r"(a) : "l"(p));
    return a;
}

// ---------------------------------------------------------------------------
// Kernel 0: zero W scratch + convert F -> fp16
// ---------------------------------------------------------------------------
__global__ void zero_conv_kernel(const float* __restrict__ F, int nW, int nF) {
    int i = blockIdx.x * blockDim.x + threadIdx.x;
    int stride = gridDim.x * blockDim.x;
    int nW4 = nW >> 2;
    float4* w4 = reinterpret_cast<float4*>(g_W);
    for (int j = i; j < nW4; j += stride) w4[j] = make_float4(0.f, 0.f, 0.f, 0.f);

    int nF4 = nF >> 2;
    const float4* f4 = reinterpret_cast<const float4*>(F);
    uint2* o4 = reinterpret_cast<uint2*>(g_Fh);
    for (int j = i; j < nF4; j += stride) {
        float4 v = f4[j];
        __half2 h01 = __floats2half2_rn(v.x, v.y);
        __half2 h23 = __floats2half2_rn(v.z, v.w);
        uint2 o;
        o.x = *reinterpret_cast<uint32_t*>(&h01);
        o.y = *reinterpret_cast<uint32_t*>(&h23);
        o4[j] = o;
    }
}

// ---------------------------------------------------------------------------
// Kernel 1: per-point 3-NN; exact branchless top-3 with warp-vote skip.
// (FROZEN R12 version)
// ---------------------------------------------------------------------------
__global__ void nn_kernel(const float* __restrict__ centers,  // (B, G, 3)
                          const float* __restrict__ points,   // (B, N, 3)
                          const int*   __restrict__ nzidx,    // (N)
                          int G, int N, int Ho, int ks) {
    extern __shared__ float4 sc[];   // G entries: (x, y, z, |s|^2)
    const int b = blockIdx.y;

    const float* cb = centers + (size_t)b * G * 3;
    for (int g = threadIdx.x; g < G; g += blockDim.x) {
        float x = cb[g * 3 + 0];
        float y = cb[g * 3 + 1];
        float z = cb[g * 3 + 2];
        sc[g] = make_float4(x, y, z, x * x + y * y + z * z);
    }
    __syncthreads();

    int nr = blockIdx.x * blockDim.x + threadIdx.x;
    bool valid = nr < N;
    int n = valid ? nr : 0;

    const float* p = points + ((size_t)b * N + n) * 3;
    float tx = p[0], ty = p[1], tz = p[2];
    float ax = -2.0f * tx, ay = -2.0f * ty, az = -2.0f * tz;
    float tt = tx * tx + ty * ty + tz * tz;

    float e0 = 3.4e38f, e1 = 3.4e38f, e2 = 3.4e38f;
    int   i0 = 0, i1 = 0, i2 = 0;

#pragma unroll 4
    for (int g = 0; g < G; g++) {
        float4 c = sc[g];
        float d = fmaf(ax, c.x, fmaf(ay, c.y, fmaf(az, c.z, c.w)));
        bool p2 = d < e2;
        if (__any_sync(0xFFFFFFFFu, p2)) {      // warp-uniform skip
            bool p0 = d < e0;
            bool p1 = d < e1;
            e2 = p1 ? e1 : (p2 ? d : e2);
            i2 = p1 ? i1 : (p2 ? g : i2);
            e1 = p0 ? e0 : (p1 ? d : e1);
            i1 = p0 ? i0 : (p1 ? g : i1);
            e0 = p0 ? d : e0;
            i0 = p0 ? g : i0;
        }
    }

    if (valid) {
        float d0 = fmaxf(e0 + tt, 1e-10f);
        float d1 = fmaxf(e1 + tt, 1e-10f);
        float d2 = fmaxf(e2 + tt, 1e-10f);
        float r0 = 1.0f / d0, r1 = 1.0f / d1, r2 = 1.0f / d2;
        float inv = 1.0f / ((r0 + r1 + r2) * (float)(ks * ks));

        int idx = nzidx[n];
        int row = idx / IMAGE_SIZE;
        int col = idx - row * IMAGE_SIZE;
        int cell = (row / ks) * Ho + (col / ks);

        float* Wrow = g_W + ((size_t)b * Ho * Ho + cell) * G;
        atomicAdd(Wrow + i0, r0 * inv);
        atomicAdd(Wrow + i1, r1 * inv);
        atomicAdd(Wrow + i2, r2 * inv);
    }
}

// ---------------------------------------------------------------------------
// Kernel 1b: convert accumulated W (fp32) -> fp16
// ---------------------------------------------------------------------------
__global__ void convw_kernel(int nW) {
    int i = blockIdx.x * blockDim.x + threadIdx.x;
    int stride = gridDim.x * blockDim.x;
    int nW4 = nW >> 2;
    const float4* w4 = reinterpret_cast<const float4*>(g_W);
    uint2* o4 = reinterpret_cast<uint2*>(g_Wh);
    for (int j = i; j < nW4; j += stride) {
        float4 v = w4[j];
        __half2 h01 = __floats2half2_rn(v.x, v.y);
        __half2 h23 = __floats2half2_rn(v.z, v.w);
        uint2 o;
        o.x = *reinterpret_cast<uint32_t*>(&h01);
        o.y = *reinterpret_cast<uint32_t*>(&h23);
        o4[j] = o;
    }
}

// ---------------------------------------------------------------------------
// Kernel 2: wmma fp16 GEMM (fp32 accum), split-K = 2, 3-stage cp.async ring.
// CTA: 128(d) x 64(c), 8 warps (4x2), warp tile 32x32 (2x2 m16n16k16).
// grid: (HoHo/64, Dim/128, B*2).  Epilogue: smem stage + float4 stores.
// ---------------------------------------------------------------------------
#define KC 32
#define A_LDM 136
#define B_LDM 40
#define A_SZ (KC * A_LDM)     // 4352 halves
#define B_SZ (64 * B_LDM)     // 2560 halves
#define ST_LDM 72
#define STAGES 3

struct __align__(32) GSmem {
    union {
        struct { __half As[STAGES][A_SZ]; __half Bs[STAGES][B_SZ]; } b;  // 41.5 KB
        float stage[128 * ST_LDM];                                       // 36.9 KB
    };
};

__global__ void __launch_bounds__(256) gemm_wmma_kernel(
        float* __restrict__ out,       // (B, Dim, HoHo)
        int G, int Dim, int HoHo) {
    __shared__ GSmem sm;

    const int tid = threadIdx.x;
    const int wid = tid >> 5;
    const int wy = wid >> 1;
    const int wx = wid & 1;
    const int bz = blockIdx.z;
    const int b     = bz >> 1;
    const int slice = bz & 1;
    const int d0 = blockIdx.y * 128;
    const int c0 = blockIdx.x * 64;

    const int Kh    = G >> 1;
    const int kbase = slice * Kh;

    const __half* Fb = g_Fh + (size_t)b * G * Dim;
    const __half* Wb = g_Wh + (size_t)b * HoHo * G;
    float* dst = slice ? g_P : out;

    const uint32_t smA = smem_u32(sm.b.As[0]);
    const uint32_t smB = smem_u32(sm.b.Bs[0]);

    wmma::fragment<wmma::accumulator, 16, 16, 16, float> acc[2][2];
#pragma unroll
    for (int i = 0; i < 2; i++)
#pragma unroll
        for (int j = 0; j < 2; j++) wmma::fill_fragment(acc[i][j], 0.0f);

    auto load_chunk = [&](int c, int buf) {
        const int g0 = kbase + c * KC;
#pragma unroll
        for (int r = 0; r < 2; r++) {
            int op = r * 256 + tid;
            int k  = op >> 4;
            int d8 = op & 15;
            const __half* src = Fb + (size_t)(g0 + k) * Dim + d0 + d8 * 8;
            int bytes = (d0 + d8 * 8 + 8 <= Dim) ? 16 : 0;
            cp_async16(smA + (uint32_t)(buf * A_SZ + k * A_LDM + d8 * 8) * 2, src, bytes);
        }
        {
            int n  = tid >> 2;
            int kq = tid & 3;
            const __half* src = Wb + (size_t)(c0 + n) * G + g0 + kq * 8;
            int bytes = (c0 + n < HoHo) ? 16 : 0;
            cp_async16(smB + (uint32_t)(buf * B_SZ + n * B_LDM + kq * 8) * 2, src, bytes);
        }
        cp_commit();
    };

    const int NC = Kh / KC;           // 8 here
    load_chunk(0, 0);
    if (NC > 1) load_chunk(1, 1);

    for (int c = 0; c < NC; c++) {
        const int buf = c % STAGES;
        if (c + 2 < NC) {
            load_chunk(c + 2, (c + 2) % STAGES);
            asm volatile("cp.async.wait_group 2;" ::: "memory");
        } else if (c + 1 < NC) {
            asm volatile("cp.async.wait_group 1;" ::: "memory");
        } else {
            asm volatile("cp.async.wait_group 0;" ::: "memory");
        }
        __syncthreads();

        const __half* As = sm.b.As[buf];
        const __half* Bs = sm.b.Bs[buf];
#pragma unroll
        for (int ks = 0; ks < KC; ks += 16) {
            wmma::fragment<wmma::matrix_a, 16, 16, 16, __half, wmma::col_major> af[2];
            wmma::fragment<wmma::matrix_b, 16, 16, 16, __half, wmma::col_major> bf[2];
#pragma unroll
            for (int fi = 0; fi < 2; fi++)
                wmma::load_matrix_sync(af[fi], As + ks * A_LDM + wy * 32 + fi * 16, A_LDM);
#pragma unroll
            for (int fj = 0; fj < 2; fj++)
                wmma::load_matrix_sync(bf[fj], Bs + (wx * 32 + fj * 16) * B_LDM + ks, B_LDM);
#pragma unroll
            for (int fi = 0; fi < 2; fi++)
#pragma unroll
                for (int fj = 0; fj < 2; fj++)
                    wmma::mma_sync(acc[fi][fj], af[fi], bf[fj], acc[fi][fj]);
        }
        __syncthreads();
    }

    // --- epilogue: frags -> smem stage -> guarded coalesced float4 stores ---
#pragma unroll
    for (int fi = 0; fi < 2; fi++)
#pragma unroll
        for (int fj = 0; fj < 2; fj++)
            wmma::store_matrix_sync(
                sm.stage + (wy * 32 + fi * 16) * ST_LDM + wx * 32 + fj * 16,
                acc[fi][fj], ST_LDM, wmma::mem_row_major);
    __syncthreads();

    {
        const int row = tid >> 1;
        const int cb  = (tid & 1) * 32;
        const int d = d0 + row;
        if (d < Dim) {
            float* orow = dst + ((size_t)b * Dim + d) * HoHo;
            const float* srow = sm.stage + row * ST_LDM + cb;
#pragma unroll
            for (int j = 0; j < 32; j += 4) {
                int cc = c0 + cb + j;
                if (cc + 4 <= HoHo) {
                    float4 v = *reinterpret_cast<const float4*>(srow + j);
                    *reinterpret_cast<float4*>(orow + cc) = v;
                } else {
#pragma unroll
                    for (int q = 0; q < 4; q++)
                        if (cc + q < HoHo) orow[cc + q] = srow[j + q];
                }
            }
        }
    }
}

// ---------------------------------------------------------------------------
// Kernel 3: merge split-K partial sums:  out += g_P
// ---------------------------------------------------------------------------
__global__ void add_kernel(float* __restrict__ out, int nOut) {
    int i = blockIdx.x * blockDim.x + threadIdx.x;
    int stride = gridDim.x * blockDim.x;
    int n4 = nOut >> 2;
    float4* o4 = reinterpret_cast<float4*>(out);
    const float4* p4 = reinterpret_cast<const float4*>(g_P);
    for (int j = i; j < n4; j += stride) {
        float4 a = o4[j];
        float4 p = p4[j];
        a.x += p.x; a.y += p.y; a.z += p.z; a.w += p.w;
        o4[j] = a;
    }
}

// ---------------------------------------------------------------------------
// Launch
// ---------------------------------------------------------------------------
extern "C" void kernel_launch(void* const* d_in, const int* in_sizes, int n_in,
                              void* d_out, int out_size) {
    const float* group_features = (const float*)d_in[0];  // (B, G, Dim)
    const float* group_centers  = (const float*)d_in[1];  // (B, G, 3)
    const float* original_pts   = (const float*)d_in[2];  // (B, N, 3)
    const int*   nonzero_idx    = (const int*)d_in[3];    // (N)

    const int N   = in_sizes[3];
    const int B   = in_sizes[2] / (3 * N);
    const int Dim = (int)(3LL * in_sizes[0] / in_sizes[1]);
    const int G   = in_sizes[1] / (3 * B);
    const int HoHo = out_size / (B * Dim);
    int Ho = 1;
    while ((Ho + 1) * (Ho + 1) <= HoHo) Ho++;     // integer sqrt
    const int ks = IMAGE_SIZE / Ho;

    const int nW = B * HoHo * G;
    const int nF = B * G * Dim;

    zero_conv_kernel<<<512, 256>>>(group_features, nW, nF);

    dim3 nnGrid((N + 255) / 256, B);
    size_t smem = (size_t)G * sizeof(float4);
    nn_kernel<<<nnGrid, 256, smem>>>(group_centers, original_pts, nonzero_idx,
                                     G, N, Ho, ks);

    convw_kernel<<<512, 256>>>(nW);

    dim3 gGrid((HoHo + 63) / 64, (Dim + 127) / 128, B * 2);
    gemm_wmma_kernel<<<gGrid, 256>>>((float*)d_out, G, Dim, HoHo);

    add_kernel<<<296, 256>>>((float*)d_out, out_size);
}

// round 16
// speedup vs baseline: 1.5067x; 1.5067x over previous
#include <cuda_runtime.h>
#include <cuda_fp16.h>
#include <cstdint>
#include <math.h>
#include <mma.h>

using namespace nvcuda;

// ---------------------------------------------------------------------------
// PointFeatureAlignment: W[b,cell,g] (3-NN weights / 64) then
// Out[b,d,cell] = sum_g W[b,cell,g] * F[b,g,d]
// EXACT REVERT to the R12 best-measured state (59.9us):
// nn: exact branchless top-3 with warp-vote skip (selection-altering
//     transforms banned: R6/R10/R13). GEMM: wmma fp16, split-K=2, 2-stage
//     cp.async double buffer (3-stage regressed twice: R14/R15).
// ---------------------------------------------------------------------------

#define IMAGE_SIZE 224
#define MAX_W_ELEMS  (4 * 784 * 512)
#define MAX_F_ELEMS  (4 * 512 * 384)
#define MAX_O_ELEMS  (4 * 384 * 784)

__device__ float  g_W[MAX_W_ELEMS];      // fp32 atomic accumulation target
__device__ __half g_Wh[MAX_W_ELEMS];     // fp16 copy for GEMM
__device__ __half g_Fh[MAX_F_ELEMS];     // fp16 features
__device__ float  g_P[MAX_O_ELEMS];      // split-K partial sums (slice 1)

__device__ __forceinline__ void cp_async16(uint32_t dst, const void* src, int src_bytes) {
    asm volatile("cp.async.cg.shared.global [%0], [%1], 16, %2;"
                 :: "r"(dst), "l"(src), "r"(src_bytes) : "memory");
}
__device__ __forceinline__ void cp_commit() {
    asm volatile("cp.async.commit_group;" ::: "memory");
}
__device__ __forceinline__ uint32_t smem_u32(const void* p) {
    uint32_t a;
    asm("{ .reg .u64 t; cvta.to.shared.u64 t, %1; cvt.u32.u64 %0, t; }"
        : "=r"(a) : "l"(p));
    return a;
}

// ---------------------------------------------------------------------------
// Kernel 0: zero W scratch + convert F -> fp16
// ---------------------------------------------------------------------------
__global__ void zero_conv_kernel(const float* __restrict__ F, int nW, int nF) {
    int i = blockIdx.x * blockDim.x + threadIdx.x;
    int stride = gridDim.x * blockDim.x;
    int nW4 = nW >> 2;
    float4* w4 = reinterpret_cast<float4*>(g_W);
    for (int j = i; j < nW4; j += stride) w4[j] = make_float4(0.f, 0.f, 0.f, 0.f);

    int nF4 = nF >> 2;
    const float4* f4 = reinterpret_cast<const float4*>(F);
    uint2* o4 = reinterpret_cast<uint2*>(g_Fh);
    for (int j = i; j < nF4; j += stride) {
        float4 v = f4[j];
        __half2 h01 = __floats2half2_rn(v.x, v.y);
        __half2 h23 = __floats2half2_rn(v.z, v.w);
        uint2 o;
        o.x = *reinterpret_cast<uint32_t*>(&h01);
        o.y = *reinterpret_cast<uint32_t*>(&h23);
        o4[j] = o;
    }
}

// ---------------------------------------------------------------------------
// Kernel 1: per-point 3-NN; exact branchless top-3 with warp-vote skip.
// ---------------------------------------------------------------------------
__global__ void nn_kernel(const float* __restrict__ centers,  // (B, G, 3)
                          const float* __restrict__ points,   // (B, N, 3)
                          const int*   __restrict__ nzidx,    // (N)
                          int G, int N, int Ho, int ks) {
    extern __shared__ float4 sc[];   // G entries: (x, y, z, |s|^2)
    const int b = blockIdx.y;

    const float* cb = centers + (size_t)b * G * 3;
    for (int g = threadIdx.x; g < G; g += blockDim.x) {
        float x = cb[g * 3 + 0];
        float y = cb[g * 3 + 1];
        float z = cb[g * 3 + 2];
        sc[g] = make_float4(x, y, z, x * x + y * y + z * z);
    }
    __syncthreads();

    int nr = blockIdx.x * blockDim.x + threadIdx.x;
    bool valid = nr < N;
    int n = valid ? nr : 0;

    const float* p = points + ((size_t)b * N + n) * 3;
    float tx = p[0], ty = p[1], tz = p[2];
    float ax = -2.0f * tx, ay = -2.0f * ty, az = -2.0f * tz;
    float tt = tx * tx + ty * ty + tz * tz;

    float e0 = 3.4e38f, e1 = 3.4e38f, e2 = 3.4e38f;
    int   i0 = 0, i1 = 0, i2 = 0;

#pragma unroll 4
    for (int g = 0; g < G; g++) {
        float4 c = sc[g];
        float d = fmaf(ax, c.x, fmaf(ay, c.y, fmaf(az, c.z, c.w)));
        bool p2 = d < e2;
        if (__any_sync(0xFFFFFFFFu, p2)) {      // warp-uniform skip
            bool p0 = d < e0;
            bool p1 = d < e1;
            e2 = p1 ? e1 : (p2 ? d : e2);
            i2 = p1 ? i1 : (p2 ? g : i2);
            e1 = p0 ? e0 : (p1 ? d : e1);
            i1 = p0 ? i0 : (p1 ? g : i1);
            e0 = p0 ? d : e0;
            i0 = p0 ? g : i0;
        }
    }

    if (valid) {
        float d0 = fmaxf(e0 + tt, 1e-10f);
        float d1 = fmaxf(e1 + tt, 1e-10f);
        float d2 = fmaxf(e2 + tt, 1e-10f);
        float r0 = 1.0f / d0, r1 = 1.0f / d1, r2 = 1.0f / d2;
        float inv = 1.0f / ((r0 + r1 + r2) * (float)(ks * ks));

        int idx = nzidx[n];
        int row = idx / IMAGE_SIZE;
        int col = idx - row * IMAGE_SIZE;
        int cell = (row / ks) * Ho + (col / ks);

        float* Wrow = g_W + ((size_t)b * Ho * Ho + cell) * G;
        atomicAdd(Wrow + i0, r0 * inv);
        atomicAdd(Wrow + i1, r1 * inv);
        atomicAdd(Wrow + i2, r2 * inv);
    }
}

// ---------------------------------------------------------------------------
// Kernel 1b: convert accumulated W (fp32) -> fp16
// ---------------------------------------------------------------------------
__global__ void convw_kernel(int nW) {
    int i = blockIdx.x * blockDim.x + threadIdx.x;
    int stride = gridDim.x * blockDim.x;
    int nW4 = nW >> 2;
    const float4* w4 = reinterpret_cast<const float4*>(g_W);
    uint2* o4 = reinterpret_cast<uint2*>(g_Wh);
    for (int j = i; j < nW4; j += stride) {
        float4 v = w4[j];
        __half2 h01 = __floats2half2_rn(v.x, v.y);
        __half2 h23 = __floats2half2_rn(v.z, v.w);
        uint2 o;
        o.x = *reinterpret_cast<uint32_t*>(&h01);
        o.y = *reinterpret_cast<uint32_t*>(&h23);
        o4[j] = o;
    }
}

// ---------------------------------------------------------------------------
// Kernel 2: wmma fp16 GEMM (fp32 accum), split-K = 2, 2-stage double buffer.
// CTA: 128(d) x 64(c), 8 warps (4x2), warp tile 32x32 (2x2 m16n16k16).
// grid: (HoHo/64, Dim/128, B*2).
// ---------------------------------------------------------------------------
#define KC 32
#define A_LDM 136
#define B_LDM 40
#define A_SZ (KC * A_LDM)     // 4352 halves
#define B_SZ (64 * B_LDM)     // 2560 halves
#define ST_LDM 72

struct __align__(32) GSmem {
    union {
        struct { __half As[2][A_SZ]; __half Bs[2][B_SZ]; } b;   // 27.6 KB
        float stage[128 * ST_LDM];                              // 36.9 KB
    };
};

__global__ void __launch_bounds__(256) gemm_wmma_kernel(
        float* __restrict__ out,       // (B, Dim, HoHo)
        int G, int Dim, int HoHo) {
    __shared__ GSmem sm;

    const int tid = threadIdx.x;
    const int wid = tid >> 5;
    const int wy = wid >> 1;
    const int wx = wid & 1;
    const int bz = blockIdx.z;
    const int b     = bz >> 1;
    const int slice = bz & 1;
    const int d0 = blockIdx.y * 128;
    const int c0 = blockIdx.x * 64;

    const int Kh    = G >> 1;
    const int kbase = slice * Kh;

    const __half* Fb = g_Fh + (size_t)b * G * Dim;
    const __half* Wb = g_Wh + (size_t)b * HoHo * G;
    float* dst = slice ? g_P : out;

    const uint32_t smA = smem_u32(sm.b.As[0]);
    const uint32_t smB = smem_u32(sm.b.Bs[0]);

    wmma::fragment<wmma::accumulator, 16, 16, 16, float> acc[2][2];
#pragma unroll
    for (int i = 0; i < 2; i++)
#pragma unroll
        for (int j = 0; j < 2; j++) wmma::fill_fragment(acc[i][j], 0.0f);

    auto load_chunk = [&](int c, int buf) {
        const int g0 = kbase + c * KC;
#pragma unroll
        for (int r = 0; r < 2; r++) {
            int op = r * 256 + tid;
            int k  = op >> 4;
            int d8 = op & 15;
            const __half* src = Fb + (size_t)(g0 + k) * Dim + d0 + d8 * 8;
            int bytes = (d0 + d8 * 8 + 8 <= Dim) ? 16 : 0;
            cp_async16(smA + (uint32_t)(buf * A_SZ + k * A_LDM + d8 * 8) * 2, src, bytes);
        }
        {
            int n  = tid >> 2;
            int kq = tid & 3;
            const __half* src = Wb + (size_t)(c0 + n) * G + g0 + kq * 8;
            int bytes = (c0 + n < HoHo) ? 16 : 0;
            cp_async16(smB + (uint32_t)(buf * B_SZ + n * B_LDM + kq * 8) * 2, src, bytes);
        }
        cp_commit();
    };

    const int NC = Kh / KC;   // 8 for G=512
    load_chunk(0, 0);

    for (int c = 0; c < NC; c++) {
        const int buf = c & 1;
        if (c + 1 < NC) {
            load_chunk(c + 1, (c + 1) & 1);
            asm volatile("cp.async.wait_group 1;" ::: "memory");
        } else {
            asm volatile("cp.async.wait_group 0;" ::: "memory");
        }
        __syncthreads();

        const __half* As = sm.b.As[buf];
        const __half* Bs = sm.b.Bs[buf];
#pragma unroll
        for (int ks = 0; ks < KC; ks += 16) {
            wmma::fragment<wmma::matrix_a, 16, 16, 16, __half, wmma::col_major> af[2];
            wmma::fragment<wmma::matrix_b, 16, 16, 16, __half, wmma::col_major> bf[2];
#pragma unroll
            for (int fi = 0; fi < 2; fi++)
                wmma::load_matrix_sync(af[fi], As + ks * A_LDM + wy * 32 + fi * 16, A_LDM);
#pragma unroll
            for (int fj = 0; fj < 2; fj++)
                wmma::load_matrix_sync(bf[fj], Bs + (wx * 32 + fj * 16) * B_LDM + ks, B_LDM);
#pragma unroll
            for (int fi = 0; fi < 2; fi++)
#pragma unroll
                for (int fj = 0; fj < 2; fj++)
                    wmma::mma_sync(acc[fi][fj], af[fi], bf[fj], acc[fi][fj]);
        }
        __syncthreads();
    }

    // --- epilogue: frags -> smem stage -> guarded coalesced float4 stores ---
#pragma unroll
    for (int fi = 0; fi < 2; fi++)
#pragma unroll
        for (int fj = 0; fj < 2; fj++)
            wmma::store_matrix_sync(
                sm.stage + (wy * 32 + fi * 16) * ST_LDM + wx * 32 + fj * 16,
                acc[fi][fj], ST_LDM, wmma::mem_row_major);
    __syncthreads();

    {
        const int row = tid >> 1;
        const int cb  = (tid & 1) * 32;
        const int d = d0 + row;
        if (d < Dim) {
            float* orow = dst + ((size_t)b * Dim + d) * HoHo;
            const float* srow = sm.stage + row * ST_LDM + cb;
#pragma unroll
            for (int j = 0; j < 32; j += 4) {
                int cc = c0 + cb + j;
                if (cc + 4 <= HoHo) {
                    float4 v = *reinterpret_cast<const float4*>(srow + j);
                    *reinterpret_cast<float4*>(orow + cc) = v;
                } else {
#pragma unroll
                    for (int q = 0; q < 4; q++)
                        if (cc + q < HoHo) orow[cc + q] = srow[j + q];
                }
            }
        }
    }
}

// ---------------------------------------------------------------------------
// Kernel 3: merge split-K partial sums:  out += g_P
// ---------------------------------------------------------------------------
__global__ void add_kernel(float* __restrict__ out, int nOut) {
    int i = blockIdx.x * blockDim.x + threadIdx.x;
    int stride = gridDim.x * blockDim.x;
    int n4 = nOut >> 2;
    float4* o4 = reinterpret_cast<float4*>(out);
    const float4* p4 = reinterpret_cast<const float4*>(g_P);
    for (int j = i; j < n4; j += stride) {
        float4 a = o4[j];
        float4 p = p4[j];
        a.x += p.x; a.y += p.y; a.z += p.z; a.w += p.w;
        o4[j] = a;
    }
}

// ---------------------------------------------------------------------------
// Launch
// ---------------------------------------------------------------------------
extern "C" void kernel_launch(void* const* d_in, const int* in_sizes, int n_in,
                              void* d_out, int out_size) {
    const float* group_features = (const float*)d_in[0];  // (B, G, Dim)
    const float* group_centers  = (const float*)d_in[1];  // (B, G, 3)
    const float* original_pts   = (const float*)d_in[2];  // (B, N, 3)
    const int*   nonzero_idx    = (const int*)d_in[3];    // (N)

    const int N   = in_sizes[3];
    const int B   = in_sizes[2] / (3 * N);
    const int Dim = (int)(3LL * in_sizes[0] / in_sizes[1]);
    const int G   = in_sizes[1] / (3 * B);
    const int HoHo = out_size / (B * Dim);
    int Ho = 1;
    while ((Ho + 1) * (Ho + 1) <= HoHo) Ho++;     // integer sqrt
    const int ks = IMAGE_SIZE / Ho;

    const int nW = B * HoHo * G;
    const int nF = B * G * Dim;

    zero_conv_kernel<<<512, 256>>>(group_features, nW, nF);

    dim3 nnGrid((N + 255) / 256, B);
    size_t smem = (size_t)G * sizeof(float4);
    nn_kernel<<<nnGrid, 256, smem>>>(group_centers, original_pts, nonzero_idx,
                                     G, N, Ho, ks);

    convw_kernel<<<512, 256>>>(nW);

    dim3 gGrid((HoHo + 63) / 64, (Dim + 127) / 128, B * 2);
    gemm_wmma_kernel<<<gGrid, 256>>>((float*)d_out, G, Dim, HoHo);

    add_kernel<<<296, 256>>>((float*)d_out, out_size);
}

// round 17
// speedup vs baseline: 1.5667x; 1.0398x over previous
#include <cuda_runtime.h>
#include <cuda_fp16.h>
#include <cstdint>
#include <math.h>
#include <mma.h>

using namespace nvcuda;

// ---------------------------------------------------------------------------
// PointFeatureAlignment: W[b,cell,g] (3-NN weights / 64) then
// Out[b,d,cell] = sum_g W[b,cell,g] * F[b,g,d]
// nn: exact branchless top-3 with warp-vote skip (selection-altering
//     transforms banned: R6/R10/R13 evidence).
// GEMM: wmma fp16 m16n16k16, fp32 accum, split-K=2, 2-stage cp.async for A;
//       B (W) loaded as fp32 with register prefetch and converted in-kernel
//       with __floats2half2_rn (same rounding as the old convw pass ->
//       bit-identical MMA inputs). convw kernel ELIMINATED.
// ---------------------------------------------------------------------------

#define IMAGE_SIZE 224
#define MAX_W_ELEMS  (4 * 784 * 512)
#define MAX_F_ELEMS  (4 * 512 * 384)
#define MAX_O_ELEMS  (4 * 384 * 784)

__device__ float  g_W[MAX_W_ELEMS];      // fp32 atomic accumulation target
__device__ __half g_Fh[MAX_F_ELEMS];     // fp16 features
__device__ float  g_P[MAX_O_ELEMS];      // split-K partial sums (slice 1)

__device__ __forceinline__ void cp_async16(uint32_t dst, const void* src, int src_bytes) {
    asm volatile("cp.async.cg.shared.global [%0], [%1], 16, %2;"
                 :: "r"(dst), "l"(src), "r"(src_bytes) : "memory");
}
__device__ __forceinline__ void cp_commit() {
    asm volatile("cp.async.commit_group;" ::: "memory");
}
__device__ __forceinline__ uint32_t smem_u32(const void* p) {
    uint32_t a;
    asm("{ .reg .u64 t; cvta.to.shared.u64 t, %1; cvt.u32.u64 %0, t; }"
        : "=r"(a) : "l"(p));
    return a;
}

// ---------------------------------------------------------------------------
// Kernel 0: zero W scratch + convert F -> fp16
// ---------------------------------------------------------------------------
__global__ void zero_conv_kernel(const float* __restrict__ F, int nW, int nF) {
    int i = blockIdx.x * blockDim.x + threadIdx.x;
    int stride = gridDim.x * blockDim.x;
    int nW4 = nW >> 2;
    float4* w4 = reinterpret_cast<float4*>(g_W);
    for (int j = i; j < nW4; j += stride) w4[j] = make_float4(0.f, 0.f, 0.f, 0.f);

    int nF4 = nF >> 2;
    const float4* f4 = reinterpret_cast<const float4*>(F);
    uint2* o4 = reinterpret_cast<uint2*>(g_Fh);
    for (int j = i; j < nF4; j += stride) {
        float4 v = f4[j];
        __half2 h01 = __floats2half2_rn(v.x, v.y);
        __half2 h23 = __floats2half2_rn(v.z, v.w);
        uint2 o;
        o.x = *reinterpret_cast<uint32_t*>(&h01);
        o.y = *reinterpret_cast<uint32_t*>(&h23);
        o4[j] = o;
    }
}

// ---------------------------------------------------------------------------
// Kernel 1: per-point 3-NN; exact branchless top-3 with warp-vote skip.
// ---------------------------------------------------------------------------
__global__ void nn_kernel(const float* __restrict__ centers,  // (B, G, 3)
                          const float* __restrict__ points,   // (B, N, 3)
                          const int*   __restrict__ nzidx,    // (N)
                          int G, int N, int Ho, int ks) {
    extern __shared__ float4 sc[];   // G entries: (x, y, z, |s|^2)
    const int b = blockIdx.y;

    const float* cb = centers + (size_t)b * G * 3;
    for (int g = threadIdx.x; g < G; g += blockDim.x) {
        float x = cb[g * 3 + 0];
        float y = cb[g * 3 + 1];
        float z = cb[g * 3 + 2];
        sc[g] = make_float4(x, y, z, x * x + y * y + z * z);
    }
    __syncthreads();

    int nr = blockIdx.x * blockDim.x + threadIdx.x;
    bool valid = nr < N;
    int n = valid ? nr : 0;

    const float* p = points + ((size_t)b * N + n) * 3;
    float tx = p[0], ty = p[1], tz = p[2];
    float ax = -2.0f * tx, ay = -2.0f * ty, az = -2.0f * tz;
    float tt = tx * tx + ty * ty + tz * tz;

    float e0 = 3.4e38f, e1 = 3.4e38f, e2 = 3.4e38f;
    int   i0 = 0, i1 = 0, i2 = 0;

#pragma unroll 8
    for (int g = 0; g < G; g++) {
        float4 c = sc[g];
        float d = fmaf(ax, c.x, fmaf(ay, c.y, fmaf(az, c.z, c.w)));
        bool p2 = d < e2;
        if (__any_sync(0xFFFFFFFFu, p2)) {      // warp-uniform skip
            bool p0 = d < e0;
            bool p1 = d < e1;
            e2 = p1 ? e1 : (p2 ? d : e2);
            i2 = p1 ? i1 : (p2 ? g : i2);
            e1 = p0 ? e0 : (p1 ? d : e1);
            i1 = p0 ? i0 : (p1 ? g : i1);
            e0 = p0 ? d : e0;
            i0 = p0 ? g : i0;
        }
    }

    if (valid) {
        float d0 = fmaxf(e0 + tt, 1e-10f);
        float d1 = fmaxf(e1 + tt, 1e-10f);
        float d2 = fmaxf(e2 + tt, 1e-10f);
        float r0 = 1.0f / d0, r1 = 1.0f / d1, r2 = 1.0f / d2;
        float inv = 1.0f / ((r0 + r1 + r2) * (float)(ks * ks));

        int idx = nzidx[n];
        int row = idx / IMAGE_SIZE;
        int col = idx - row * IMAGE_SIZE;
        int cell = (row / ks) * Ho + (col / ks);

        float* Wrow = g_W + ((size_t)b * Ho * Ho + cell) * G;
        atomicAdd(Wrow + i0, r0 * inv);
        atomicAdd(Wrow + i1, r1 * inv);
        atomicAdd(Wrow + i2, r2 * inv);
    }
}

// ---------------------------------------------------------------------------
// Kernel 2: wmma fp16 GEMM (fp32 accum), split-K = 2, 2-stage double buffer.
// A (features) via cp.async from g_Fh; B (W) loaded fp32 with register
// prefetch one chunk ahead, converted RN to fp16 in-kernel, stored to smem.
// CTA: 128(d) x 64(c), 8 warps (4x2), warp tile 32x32 (2x2 m16n16k16).
// grid: (HoHo/64, Dim/128, B*2).
// ---------------------------------------------------------------------------
#define KC 32
#define A_LDM 136
#define B_LDM 40
#define A_SZ (KC * A_LDM)     // 4352 halves
#define B_SZ (64 * B_LDM)     // 2560 halves
#define ST_LDM 72

struct __align__(32) GSmem {
    union {
        struct { __half As[2][A_SZ]; __half Bs[2][B_SZ]; } b;   // 27.6 KB
        float stage[128 * ST_LDM];                              // 36.9 KB
    };
};

__global__ void __launch_bounds__(256) gemm_wmma_kernel(
        float* __restrict__ out,       // (B, Dim, HoHo)
        int G, int Dim, int HoHo) {
    __shared__ GSmem sm;

    const int tid = threadIdx.x;
    const int wid = tid >> 5;
    const int wy = wid >> 1;
    const int wx = wid & 1;
    const int bz = blockIdx.z;
    const int b     = bz >> 1;
    const int slice = bz & 1;
    const int d0 = blockIdx.y * 128;
    const int c0 = blockIdx.x * 64;

    const int Kh    = G >> 1;
    const int kbase = slice * Kh;

    const __half* Fb = g_Fh + (size_t)b * G * Dim;
    const float*  Wb = g_W + (size_t)b * HoHo * G;
    float* dst = slice ? g_P : out;

    const uint32_t smA = smem_u32(sm.b.As[0]);

    wmma::fragment<wmma::accumulator, 16, 16, 16, float> acc[2][2];
#pragma unroll
    for (int i = 0; i < 2; i++)
#pragma unroll
        for (int j = 0; j < 2; j++) wmma::fill_fragment(acc[i][j], 0.0f);

    // A-tile async load (fp16, 2 x cp.async per thread)
    auto load_chunk_A = [&](int c, int buf) {
        const int g0 = kbase + c * KC;
#pragma unroll
        for (int r = 0; r < 2; r++) {
            int op = r * 256 + tid;
            int k  = op >> 4;
            int d8 = op & 15;
            const __half* src = Fb + (size_t)(g0 + k) * Dim + d0 + d8 * 8;
            int bytes = (d0 + d8 * 8 + 8 <= Dim) ? 16 : 0;
            cp_async16(smA + (uint32_t)(buf * A_SZ + k * A_LDM + d8 * 8) * 2, src, bytes);
        }
        cp_commit();
    };

    // B-tile fp32 register load (thread t: row n = t>>2, 8 k-floats at kq*8)
    const int Bn  = tid >> 2;
    const int Bkq = tid & 3;
    auto ldg_B = [&](int c, float4* r) {
        const int g0 = kbase + c * KC;
        if (c0 + Bn < HoHo) {
            const float* src = Wb + (size_t)(c0 + Bn) * G + g0 + Bkq * 8;
            r[0] = *reinterpret_cast<const float4*>(src);
            r[1] = *reinterpret_cast<const float4*>(src + 4);
        } else {
            r[0] = make_float4(0.f, 0.f, 0.f, 0.f);
            r[1] = make_float4(0.f, 0.f, 0.f, 0.f);
        }
    };
    auto sts_B = [&](int buf, const float4* r) {
        __half2 h0 = __floats2half2_rn(r[0].x, r[0].y);
        __half2 h1 = __floats2half2_rn(r[0].z, r[0].w);
        __half2 h2 = __floats2half2_rn(r[1].x, r[1].y);
        __half2 h3 = __floats2half2_rn(r[1].z, r[1].w);
        uint4 pack;
        pack.x = *reinterpret_cast<uint32_t*>(&h0);
        pack.y = *reinterpret_cast<uint32_t*>(&h1);
        pack.z = *reinterpret_cast<uint32_t*>(&h2);
        pack.w = *reinterpret_cast<uint32_t*>(&h3);
        *reinterpret_cast<uint4*>(&sm.b.Bs[buf][Bn * B_LDM + Bkq * 8]) = pack;
    };

    const int NC = Kh / KC;   // 8 for G=512
    float4 rB[2], rB2[2];
    load_chunk_A(0, 0);
    ldg_B(0, rB);

    for (int c = 0; c < NC; c++) {
        const int buf = c & 1;
        if (c + 1 < NC) {
            load_chunk_A(c + 1, (c + 1) & 1);
            ldg_B(c + 1, rB2);
            sts_B(buf, rB);
            asm volatile("cp.async.wait_group 1;" ::: "memory");
        } else {
            sts_B(buf, rB);
            asm volatile("cp.async.wait_group 0;" ::: "memory");
        }
        __syncthreads();

        const __half* As = sm.b.As[buf];
        const __half* Bs = sm.b.Bs[buf];
#pragma unroll
        for (int ks = 0; ks < KC; ks += 16) {
            wmma::fragment<wmma::matrix_a, 16, 16, 16, __half, wmma::col_major> af[2];
            wmma::fragment<wmma::matrix_b, 16, 16, 16, __half, wmma::col_major> bf[2];
#pragma unroll
            for (int fi = 0; fi < 2; fi++)
                wmma::load_matrix_sync(af[fi], As + ks * A_LDM + wy * 32 + fi * 16, A_LDM);
#pragma unroll
            for (int fj = 0; fj < 2; fj++)
                wmma::load_matrix_sync(bf[fj], Bs + (wx * 32 + fj * 16) * B_LDM + ks, B_LDM);
#pragma unroll
            for (int fi = 0; fi < 2; fi++)
#pragma unroll
                for (int fj = 0; fj < 2; fj++)
                    wmma::mma_sync(acc[fi][fj], af[fi], bf[fj], acc[fi][fj]);
        }
        __syncthreads();

        rB[0] = rB2[0];
        rB[1] = rB2[1];
    }

    // --- epilogue: frags -> smem stage -> guarded coalesced float4 stores ---
#pragma unroll
    for (int fi = 0; fi < 2; fi++)
#pragma unroll
        for (int fj = 0; fj < 2; fj++)
            wmma::store_matrix_sync(
                sm.stage + (wy * 32 + fi * 16) * ST_LDM + wx * 32 + fj * 16,
                acc[fi][fj], ST_LDM, wmma::mem_row_major);
    __syncthreads();

    {
        const int row = tid >> 1;
        const int cb  = (tid & 1) * 32;
        const int d = d0 + row;
        if (d < Dim) {
            float* orow = dst + ((size_t)b * Dim + d) * HoHo;
            const float* srow = sm.stage + row * ST_LDM + cb;
#pragma unroll
            for (int j = 0; j < 32; j += 4) {
                int cc = c0 + cb + j;
                if (cc + 4 <= HoHo) {
                    float4 v = *reinterpret_cast<const float4*>(srow + j);
                    *reinterpret_cast<float4*>(orow + cc) = v;
                } else {
#pragma unroll
                    for (int q = 0; q < 4; q++)
                        if (cc + q < HoHo) orow[cc + q] = srow[j + q];
                }
            }
        }
    }
}

// ---------------------------------------------------------------------------
// Kernel 3: merge split-K partial sums:  out += g_P
// ---------------------------------------------------------------------------
__global__ void add_kernel(float* __restrict__ out, int nOut) {
    int i = blockIdx.x * blockDim.x + threadIdx.x;
    int stride = gridDim.x * blockDim.x;
    int n4 = nOut >> 2;
    float4* o4 = reinterpret_cast<float4*>(out);
    const float4* p4 = reinterpret_cast<const float4*>(g_P);
    for (int j = i; j < n4; j += stride) {
        float4 a = o4[j];
        float4 p = p4[j];
        a.x += p.x; a.y += p.y; a.z += p.z; a.w += p.w;
        o4[j] = a;
    }
}

// ---------------------------------------------------------------------------
// Launch
// ---------------------------------------------------------------------------
extern "C" void kernel_launch(void* const* d_in, const int* in_sizes, int n_in,
                              void* d_out, int out_size) {
    const float* group_features = (const float*)d_in[0];  // (B, G, Dim)
    const float* group_centers  = (const float*)d_in[1];  // (B, G, 3)
    const float* original_pts   = (const float*)d_in[2];  // (B, N, 3)
    const int*   nonzero_idx    = (const int*)d_in[3];    // (N)

    const int N   = in_sizes[3];
    const int B   = in_sizes[2] / (3 * N);
    const int Dim = (int)(3LL * in_sizes[0] / in_sizes[1]);
    const int G   = in_sizes[1] / (3 * B);
    const int HoHo = out_size / (B * Dim);
    int Ho = 1;
    while ((Ho + 1) * (Ho + 1) <= HoHo) Ho++;     // integer sqrt
    const int ks = IMAGE_SIZE / Ho;

    const int nW = B * HoHo * G;
    const int nF = B * G * Dim;

    zero_conv_kernel<<<512, 256>>>(group_features, nW, nF);

    dim3 nnGrid((N + 255) / 256, B);
    size_t smem = (size_t)G * sizeof(float4);
    nn_kernel<<<nnGrid, 256, smem>>>(group_centers, original_pts, nonzero_idx,
                                     G, N, Ho, ks);

    dim3 gGrid((HoHo + 63) / 64, (Dim + 127) / 128, B * 2);
    gemm_wmma_kernel<<<gGrid, 256>>>((float*)d_out, G, Dim, HoHo);

    add_kernel<<<296, 256>>>((float*)d_out, out_size);
}